// round 7
// baseline (speedup 1.0000x reference)
#include <cuda_runtime.h>

#define BB 16
#define SS 4096
#define HH 1024
#define QD 1024
#define KD 2048
#define SSPLIT 32
#define SCHUNK (SS / SSPLIT)   // 128

// Scratch (no allocation allowed anywhere)
__device__ float g_q[BB * HH];                 // 64 KB
__device__ float g_escore[BB * SS];            // 256 KB unnormalized exp(score)
__device__ float g_partial[SSPLIT * BB * KD];  // 4 MB unnormalized ctx partials

__device__ __forceinline__ float tanh_fast(float x) {
    float y;
    asm("tanh.approx.f32 %0, %1;" : "=f"(y) : "f"(x));
    return y;
}

// ---------------------------------------------------------------------------
// K1: q[b,h] = query[b,:]·Wq[h,:].  Warp per h-row, all 16 batches in regs.
// Wq read once (4 MB DRAM); query (64 KB) broadcast from L2. 1024 warps.
// ---------------------------------------------------------------------------
__global__ void __launch_bounds__(256) k1_proj(const float* __restrict__ query,
                                               const float* __restrict__ Wq) {
    int h = (blockIdx.x * blockDim.x + threadIdx.x) >> 5;  // 0..1023
    int lane = threadIdx.x & 31;
    const float4* w4 = (const float4*)(Wq + (size_t)h * QD);
    const float4* q4 = (const float4*)query;

    float acc[BB];
#pragma unroll
    for (int b = 0; b < BB; b++) acc[b] = 0.f;

#pragma unroll
    for (int i = 0; i < QD / 128; i++) {
        float4 w = w4[lane + i * 32];
#pragma unroll
        for (int b = 0; b < BB; b++) {
            float4 q = q4[b * (QD / 4) + lane + i * 32];
            acc[b] += w.x * q.x + w.y * q.y + w.z * q.z + w.w * q.w;
        }
    }
#pragma unroll
    for (int b = 0; b < BB; b++) {
#pragma unroll
        for (int o = 16; o; o >>= 1) acc[b] += __shfl_xor_sync(0xffffffffu, acc[b], o);
    }
    if (lane == 0) {
#pragma unroll
        for (int b = 0; b < BB; b++) g_q[b * HH + h] = acc[b];
    }
}

// ---------------------------------------------------------------------------
// K2: escore[b,s] = mask ? exp(sum_h w[h]*tanh(q[b,h]+pk[b,s,h])) : 0
// Warp per row; streams 256 MB of proj_key (ldcs). tanh.approx = 1 MUFU/elt.
// No max-subtraction needed: |score| <= ||w||_1 ~ 16 (clamped at 80).
// ---------------------------------------------------------------------------
__global__ void k2_scores(const float* __restrict__ pk, const float* __restrict__ w_energy,
                          const int* __restrict__ mask) {
    int row = (blockIdx.x * blockDim.x + threadIdx.x) >> 5;  // == b*SS + s
    int lane = threadIdx.x & 31;
    int b = row >> 12;  // / SS
    const float4* p4 = (const float4*)(pk + (size_t)row * HH);
    const float4* q4 = (const float4*)(g_q + (size_t)b * HH);
    const float4* w4 = (const float4*)w_energy;
    float acc = 0.f;
#pragma unroll
    for (int i = 0; i < HH / 128; i++) {
        float4 p = __ldcs(&p4[lane + i * 32]);
        float4 q = q4[lane + i * 32];
        float4 w = w4[lane + i * 32];
        acc += w.x * tanh_fast(q.x + p.x);
        acc += w.y * tanh_fast(q.y + p.y);
        acc += w.z * tanh_fast(q.z + p.z);
        acc += w.w * tanh_fast(q.w + p.w);
    }
#pragma unroll
    for (int o = 16; o; o >>= 1) acc += __shfl_xor_sync(0xffffffffu, acc, o);
    if (lane == 0)
        g_escore[row] = (mask[row] == 0) ? 0.f : __expf(fminf(acc, 80.f));
}

// ---------------------------------------------------------------------------
// K4: unnormalized partial context. grid = (KD/1024, BB, SSPLIT) = 1024 blocks.
// Streams 512 MB of value (ldcs), float4 wide.
// ---------------------------------------------------------------------------
__global__ void __launch_bounds__(256) k4_ctx(const float* __restrict__ value) {
    __shared__ float a[SCHUNK];
    int b = blockIdx.y;
    int ssec = blockIdx.z;
    int k4i = blockIdx.x * blockDim.x + threadIdx.x;
    int s0 = ssec * SCHUNK;

    if (threadIdx.x < SCHUNK)
        a[threadIdx.x] = g_escore[b * SS + s0 + threadIdx.x];
    __syncthreads();

    const float4* vp = (const float4*)(value + ((size_t)b * SS + s0) * KD) + k4i;
    float4 acc = make_float4(0.f, 0.f, 0.f, 0.f);
#pragma unroll 8
    for (int s = 0; s < SCHUNK; s++) {
        float4 v = __ldcs(&vp[(size_t)s * (KD / 4)]);
        float al = a[s];
        acc.x += al * v.x;
        acc.y += al * v.y;
        acc.z += al * v.z;
        acc.w += al * v.w;
    }
    ((float4*)(g_partial + ((size_t)ssec * BB + b) * KD))[k4i] = acc;
}

// ---------------------------------------------------------------------------
// K_fin: per batch — fixed-order sum of escore, normalize alphas, reduce+
// normalize ctx partials. All order fixed => deterministic.
// ---------------------------------------------------------------------------
__global__ void __launch_bounds__(256) k_fin(float* __restrict__ ctx,
                                             float* __restrict__ alphas) {
    int b = blockIdx.x, tid = threadIdx.x, lane = tid & 31, wid = tid >> 5;
    __shared__ float red[8];
    __shared__ float s_inv;

    float s = 0.f;
#pragma unroll
    for (int i = 0; i < SS / 256; i++)          // fixed per-thread order
        s += g_escore[b * SS + tid + i * 256];
#pragma unroll
    for (int o = 16; o; o >>= 1) s += __shfl_xor_sync(0xffffffffu, s, o);
    if (lane == 0) red[wid] = s;
    __syncthreads();
    if (tid == 0) {
        float t = 0.f;
#pragma unroll
        for (int i = 0; i < 8; i++) t += red[i]; // fixed order
        s_inv = 1.0f / t;
    }
    __syncthreads();
    float inv = s_inv;

#pragma unroll
    for (int i = 0; i < SS / 256; i++) {
        int sidx = b * SS + tid + i * 256;
        alphas[sidx] = g_escore[sidx] * inv;
    }

#pragma unroll
    for (int i = 0; i < KD / 4 / 256; i++) {     // 2 float4 iters per thread
        int k4i = tid + i * 256;
        float4 acc = make_float4(0.f, 0.f, 0.f, 0.f);
#pragma unroll
        for (int ssec = 0; ssec < SSPLIT; ssec++) {   // fixed order
            float4 v = ((const float4*)(g_partial + ((size_t)ssec * BB + b) * KD))[k4i];
            acc.x += v.x; acc.y += v.y; acc.z += v.z; acc.w += v.w;
        }
        acc.x *= inv; acc.y *= inv; acc.z *= inv; acc.w *= inv;
        ((float4*)(ctx + (size_t)b * KD))[k4i] = acc;
    }
}

extern "C" void kernel_launch(void* const* d_in, const int* in_sizes, int n_in,
                              void* d_out, int out_size) {
    const int*   mask     = (const int*)d_in[0];
    const float* query    = (const float*)d_in[1];
    const float* proj_key = (const float*)d_in[2];
    const float* value    = (const float*)d_in[3];
    const float* Wq       = (const float*)d_in[4];
    const float* w_energy = (const float*)d_in[5];

    float* out    = (float*)d_out;
    float* ctx    = out;              // (B,1,K) = 32768 floats
    float* alphas = out + BB * KD;    // (B,1,S) = 65536 floats

    k1_proj<<<128, 256>>>(query, Wq);
    k2_scores<<<BB * SS / 8, 256>>>(proj_key, w_energy, mask);
    k4_ctx<<<dim3(KD / 1024, BB, SSPLIT), 256>>>(value);
    k_fin<<<BB, 256>>>(ctx, alphas);
}

// round 8
// speedup vs baseline: 1.0206x; 1.0206x over previous
#include <cuda_runtime.h>

#define BB 16
#define SS 4096
#define HH 1024
#define QD 1024
#define KD 2048
#define SSPLIT 32
#define SCHUNK (SS / SSPLIT)   // 128

// Scratch (no allocation allowed anywhere)
__device__ float g_q[BB * HH];                 // 64 KB
__device__ float g_escore[BB * SS];            // 256 KB unnormalized exp(score)
__device__ float g_partial[SSPLIT * BB * KD];  // 4 MB unnormalized ctx partials
__device__ float g_sum[BB];

__device__ __forceinline__ float tanh_fast(float x) {
    float y;
    asm("tanh.approx.f32 %0, %1;" : "=f"(y) : "f"(x));
    return y;
}

// ---------------------------------------------------------------------------
// K1: q[b,h] = query[b,:]·Wq[h,:].  Warp per h-row, all 16 batches in regs.
// Wq read once (4 MB DRAM); query (64 KB) broadcast from L2. 1024 warps.
// ---------------------------------------------------------------------------
__global__ void __launch_bounds__(256) k1_proj(const float* __restrict__ query,
                                               const float* __restrict__ Wq) {
    int h = (blockIdx.x * blockDim.x + threadIdx.x) >> 5;  // 0..1023
    int lane = threadIdx.x & 31;
    const float4* w4 = (const float4*)(Wq + (size_t)h * QD);
    const float4* q4 = (const float4*)query;

    float acc[BB];
#pragma unroll
    for (int b = 0; b < BB; b++) acc[b] = 0.f;

#pragma unroll
    for (int i = 0; i < QD / 128; i++) {
        float4 w = w4[lane + i * 32];
#pragma unroll
        for (int b = 0; b < BB; b++) {
            float4 q = q4[b * (QD / 4) + lane + i * 32];
            acc[b] += w.x * q.x + w.y * q.y + w.z * q.z + w.w * q.w;
        }
    }
#pragma unroll
    for (int b = 0; b < BB; b++) {
#pragma unroll
        for (int o = 16; o; o >>= 1) acc[b] += __shfl_xor_sync(0xffffffffu, acc[b], o);
    }
    if (lane == 0) {
#pragma unroll
        for (int b = 0; b < BB; b++) g_q[b * HH + h] = acc[b];
    }
}

// ---------------------------------------------------------------------------
// K2: escore[b,s] = mask ? exp(sum_h w[h]*tanh(q[b,h]+pk[b,s,h])) : 0
// Warp per row; streams 256 MB of proj_key (ldcs). tanh.approx = 1 MUFU/elt.
// No max-subtraction needed: |score| <= ||w||_1 ~ 16 (clamped at 80).
// ---------------------------------------------------------------------------
__global__ void k2_scores(const float* __restrict__ pk, const float* __restrict__ w_energy,
                          const int* __restrict__ mask) {
    int row = (blockIdx.x * blockDim.x + threadIdx.x) >> 5;  // == b*SS + s
    int lane = threadIdx.x & 31;
    int b = row >> 12;  // / SS
    const float4* p4 = (const float4*)(pk + (size_t)row * HH);
    const float4* q4 = (const float4*)(g_q + (size_t)b * HH);
    const float4* w4 = (const float4*)w_energy;
    float acc = 0.f;
#pragma unroll
    for (int i = 0; i < HH / 128; i++) {
        float4 p = __ldcs(&p4[lane + i * 32]);
        float4 q = q4[lane + i * 32];
        float4 w = w4[lane + i * 32];
        acc += w.x * tanh_fast(q.x + p.x);
        acc += w.y * tanh_fast(q.y + p.y);
        acc += w.z * tanh_fast(q.z + p.z);
        acc += w.w * tanh_fast(q.w + p.w);
    }
#pragma unroll
    for (int o = 16; o; o >>= 1) acc += __shfl_xor_sync(0xffffffffu, acc, o);
    if (lane == 0)
        g_escore[row] = (mask[row] == 0) ? 0.f : __expf(fminf(acc, 80.f));
}

// ---------------------------------------------------------------------------
// K4: unnormalized partial context. grid = (KD/1024, BB, SSPLIT) = 1024 blocks.
// Streams 512 MB of value (ldcs), float4 wide.
// ---------------------------------------------------------------------------
__global__ void __launch_bounds__(256) k4_ctx(const float* __restrict__ value) {
    __shared__ float a[SCHUNK];
    int b = blockIdx.y;
    int ssec = blockIdx.z;
    int k4i = blockIdx.x * blockDim.x + threadIdx.x;
    int s0 = ssec * SCHUNK;

    if (threadIdx.x < SCHUNK)
        a[threadIdx.x] = g_escore[b * SS + s0 + threadIdx.x];
    __syncthreads();

    const float4* vp = (const float4*)(value + ((size_t)b * SS + s0) * KD) + k4i;
    float4 acc = make_float4(0.f, 0.f, 0.f, 0.f);
#pragma unroll 8
    for (int s = 0; s < SCHUNK; s++) {
        float4 v = __ldcs(&vp[(size_t)s * (KD / 4)]);
        float al = a[s];
        acc.x += al * v.x;
        acc.y += al * v.y;
        acc.z += al * v.z;
        acc.w += al * v.w;
    }
    ((float4*)(g_partial + ((size_t)ssec * BB + b) * KD))[k4i] = acc;
}

// ---------------------------------------------------------------------------
// K3s: per-batch fixed-order sum of escore -> g_sum[b]. 16 blocks x 1024 thr.
// ---------------------------------------------------------------------------
__global__ void __launch_bounds__(1024) k3_sum(int dummy) {
    int b = blockIdx.x, tid = threadIdx.x, lane = tid & 31, wid = tid >> 5;
    __shared__ float red[32];

    float s = g_escore[b * SS + tid] + g_escore[b * SS + tid + 1024]
            + g_escore[b * SS + tid + 2048] + g_escore[b * SS + tid + 3072];
#pragma unroll
    for (int o = 16; o; o >>= 1) s += __shfl_xor_sync(0xffffffffu, s, o);
    if (lane == 0) red[wid] = s;
    __syncthreads();
    if (tid == 0) {
        float t = 0.f;
#pragma unroll
        for (int i = 0; i < 32; i++) t += red[i];   // fixed order
        g_sum[b] = t;
    }
}

// ---------------------------------------------------------------------------
// K_norm: wide normalize. 96 blocks x 256 threads over 24576 float4 items:
//   items [0, 16384):  alphas = escore * inv   (float4)
//   items [16384, 24576): ctx = (fixed-order sum of 32 partials) * inv
// ---------------------------------------------------------------------------
__global__ void __launch_bounds__(256) k_norm(float* __restrict__ ctx,
                                              float* __restrict__ alphas) {
    int item = blockIdx.x * blockDim.x + threadIdx.x;
    if (item < BB * SS / 4) {
        int b = item >> 10;                     // / (SS/4)
        float inv = 1.0f / g_sum[b];
        float4 e = ((const float4*)g_escore)[item];
        e.x *= inv; e.y *= inv; e.z *= inv; e.w *= inv;
        ((float4*)alphas)[item] = e;
    } else {
        int ci = item - BB * SS / 4;            // 0 .. BB*KD/4-1
        int b = ci >> 9;                        // / (KD/4)
        int k4i = ci & (KD / 4 - 1);
        float inv = 1.0f / g_sum[b];
        float4 acc = make_float4(0.f, 0.f, 0.f, 0.f);
#pragma unroll
        for (int ssec = 0; ssec < SSPLIT; ssec++) {   // fixed order
            float4 v = ((const float4*)(g_partial + ((size_t)ssec * BB + b) * KD))[k4i];
            acc.x += v.x; acc.y += v.y; acc.z += v.z; acc.w += v.w;
        }
        acc.x *= inv; acc.y *= inv; acc.z *= inv; acc.w *= inv;
        ((float4*)(ctx + (size_t)b * KD))[k4i] = acc;
    }
}

extern "C" void kernel_launch(void* const* d_in, const int* in_sizes, int n_in,
                              void* d_out, int out_size) {
    const int*   mask     = (const int*)d_in[0];
    const float* query    = (const float*)d_in[1];
    const float* proj_key = (const float*)d_in[2];
    const float* value    = (const float*)d_in[3];
    const float* Wq       = (const float*)d_in[4];
    const float* w_energy = (const float*)d_in[5];

    float* out    = (float*)d_out;
    float* ctx    = out;              // (B,1,K) = 32768 floats
    float* alphas = out + BB * KD;    // (B,1,S) = 65536 floats

    k1_proj<<<128, 256>>>(query, Wq);
    k2_scores<<<BB * SS / 8, 256>>>(proj_key, w_energy, mask);
    k4_ctx<<<dim3(KD / 1024, BB, SSPLIT), 256>>>(value);
    k3_sum<<<BB, 1024>>>(0);
    k_norm<<<(BB * SS / 4 + BB * KD / 4) / 256, 256>>>(ctx, alphas);
}

// round 9
// speedup vs baseline: 1.6043x; 1.5720x over previous
#include <cuda_runtime.h>

#define BB 16
#define SS 4096
#define HH 1024
#define QD 1024
#define KD 2048
#define SSPLIT 32
#define SCHUNK (SS / SSPLIT)   // 128

// Scratch (no allocation allowed anywhere)
__device__ float g_q[BB * HH];                 // 64 KB
__device__ float g_escore[BB * SS];            // 256 KB unnormalized exp(score)
__device__ float g_partial[SSPLIT * BB * KD];  // 4 MB unnormalized ctx partials
__device__ float g_csum[BB * SSPLIT];          // per-chunk escore sums

__device__ __forceinline__ float tanh_fast(float x) {
    float y;
    asm("tanh.approx.f32 %0, %1;" : "=f"(y) : "f"(x));
    return y;
}

// ---------------------------------------------------------------------------
// K1: q[b,h] = query[b,:]·Wq[h,:].  Warp per h-row, all 16 batches in regs.
// Wq read once (4 MB DRAM); query (64 KB) broadcast from L2. 1024 warps.
// ---------------------------------------------------------------------------
__global__ void __launch_bounds__(256) k1_proj(const float* __restrict__ query,
                                               const float* __restrict__ Wq) {
    int h = (blockIdx.x * blockDim.x + threadIdx.x) >> 5;  // 0..1023
    int lane = threadIdx.x & 31;
    const float4* w4 = (const float4*)(Wq + (size_t)h * QD);
    const float4* q4 = (const float4*)query;

    float acc[BB];
#pragma unroll
    for (int b = 0; b < BB; b++) acc[b] = 0.f;

#pragma unroll
    for (int i = 0; i < QD / 128; i++) {
        float4 w = w4[lane + i * 32];
#pragma unroll
        for (int b = 0; b < BB; b++) {
            float4 q = q4[b * (QD / 4) + lane + i * 32];
            acc[b] += w.x * q.x + w.y * q.y + w.z * q.z + w.w * q.w;
        }
    }
#pragma unroll
    for (int b = 0; b < BB; b++) {
#pragma unroll
        for (int o = 16; o; o >>= 1) acc[b] += __shfl_xor_sync(0xffffffffu, acc[b], o);
    }
    if (lane == 0) {
#pragma unroll
        for (int b = 0; b < BB; b++) g_q[b * HH + h] = acc[b];
    }
}

// ---------------------------------------------------------------------------
// K2: escore[b,s] = mask ? exp(sum_h w[h]*tanh(q[b,h]+pk[b,s,h])) : 0
// Warp per row. MASKED ROWS SKIP THE 4KB proj_key READ (~50% of rows).
// No max-subtraction needed: |score| <= ||w||_1 ~ 16 (clamped at 80).
// ---------------------------------------------------------------------------
__global__ void k2_scores(const float* __restrict__ pk, const float* __restrict__ w_energy,
                          const int* __restrict__ mask) {
    int row = (blockIdx.x * blockDim.x + threadIdx.x) >> 5;  // == b*SS + s
    int lane = threadIdx.x & 31;

    if (mask[row] == 0) {                 // broadcast load, all lanes same addr
        if (lane == 0) g_escore[row] = 0.f;
        return;
    }

    int b = row >> 12;  // / SS
    const float4* p4 = (const float4*)(pk + (size_t)row * HH);
    const float4* q4 = (const float4*)(g_q + (size_t)b * HH);
    const float4* w4 = (const float4*)w_energy;
    float acc = 0.f;
#pragma unroll
    for (int i = 0; i < HH / 128; i++) {
        float4 p = __ldcs(&p4[lane + i * 32]);
        float4 q = q4[lane + i * 32];
        float4 w = w4[lane + i * 32];
        acc += w.x * tanh_fast(q.x + p.x);
        acc += w.y * tanh_fast(q.y + p.y);
        acc += w.z * tanh_fast(q.z + p.z);
        acc += w.w * tanh_fast(q.w + p.w);
    }
#pragma unroll
    for (int o = 16; o; o >>= 1) acc += __shfl_xor_sync(0xffffffffu, acc, o);
    if (lane == 0)
        g_escore[row] = __expf(fminf(acc, 80.f));
}

// ---------------------------------------------------------------------------
// K4: unnormalized partial context with ZERO-ROW SKIP.
// Deterministic in-order compaction of active rows, then MLP-8 loop over the
// compacted list. blockIdx.x==0 block also emits the chunk's escore sum.
// grid = (KD/1024, BB, SSPLIT) = 1024 blocks.
// ---------------------------------------------------------------------------
__global__ void __launch_bounds__(256) k4_ctx(const float* __restrict__ value) {
    __shared__ float a[SCHUNK];
    __shared__ float sa[SCHUNK + 8];
    __shared__ short sidx[SCHUNK + 8];
    __shared__ int warpcnt[4];
    __shared__ int s_nact;
    int b = blockIdx.y;
    int ssec = blockIdx.z;
    int tid = threadIdx.x;
    int s0 = ssec * SCHUNK;

    if (tid < SCHUNK)
        a[tid] = g_escore[b * SS + s0 + tid];
    __syncthreads();

    // in-order compaction (tid order => deterministic)
    if (tid < SCHUNK) {
        bool act = (a[tid] != 0.f);
        unsigned m = __ballot_sync(0xffffffffu, act);
        int lane = tid & 31, w = tid >> 5;
        if (lane == 0) warpcnt[w] = __popc(m);
    }
    __syncthreads();
    if (tid < SCHUNK) {
        bool act = (a[tid] != 0.f);
        unsigned m = __ballot_sync(0xffffffffu, act);
        int lane = tid & 31, w = tid >> 5;
        int base = 0;
#pragma unroll
        for (int i = 0; i < 4; i++) if (i < w) base += warpcnt[i];
        int pos = base + __popc(m & ((1u << lane) - 1u));
        if (act) { sa[pos] = a[tid]; sidx[pos] = (short)tid; }
        if (tid == 0) {
            int n = warpcnt[0] + warpcnt[1] + warpcnt[2] + warpcnt[3];
            int npad = (n + 7) & ~7;
            for (int j = n; j < npad; j++) { sa[j] = 0.f; sidx[j] = 0; }
            s_nact = npad;
            if (blockIdx.x == 0) {                 // chunk sum, fixed order
                float t = 0.f;
                for (int s = 0; s < SCHUNK; s++) t += a[s];
                g_csum[b * SSPLIT + ssec] = t;
            }
        }
    }
    __syncthreads();
    int nact = s_nact;

    int k4i = blockIdx.x * blockDim.x + tid;
    const float4* vp = (const float4*)(value + ((size_t)b * SS + s0) * KD) + k4i;
    float4 acc = make_float4(0.f, 0.f, 0.f, 0.f);
    for (int j = 0; j < nact; j += 8) {
#pragma unroll
        for (int u = 0; u < 8; u++) {
            float al = sa[j + u];
            int s = sidx[j + u];
            float4 v = __ldcs(&vp[(size_t)s * (KD / 4)]);
            acc.x += al * v.x;
            acc.y += al * v.y;
            acc.z += al * v.z;
            acc.w += al * v.w;
        }
    }
    ((float4*)(g_partial + ((size_t)ssec * BB + b) * KD))[k4i] = acc;
}

// ---------------------------------------------------------------------------
// K_norm: wide normalize. 96 blocks x 256 threads over 24576 float4 items.
// Each block rebuilds its batch sum from 32 chunk sums (fixed order).
//   items [0, 16384):  alphas = escore * inv
//   items [16384, 24576): ctx = (fixed-order sum of 32 partials) * inv
// ---------------------------------------------------------------------------
__global__ void __launch_bounds__(256) k_norm(float* __restrict__ ctx,
                                              float* __restrict__ alphas) {
    int item = blockIdx.x * blockDim.x + threadIdx.x;
    int b = (item < BB * SS / 4) ? (item >> 10) : ((item - BB * SS / 4) >> 9);

    float t = 0.f;
#pragma unroll
    for (int i = 0; i < SSPLIT; i++) t += g_csum[b * SSPLIT + i];  // fixed order
    float inv = 1.0f / t;

    if (item < BB * SS / 4) {
        float4 e = ((const float4*)g_escore)[item];
        e.x *= inv; e.y *= inv; e.z *= inv; e.w *= inv;
        ((float4*)alphas)[item] = e;
    } else {
        int ci = item - BB * SS / 4;            // 0 .. BB*KD/4-1
        int k4i = ci & (KD / 4 - 1);
        float4 acc = make_float4(0.f, 0.f, 0.f, 0.f);
#pragma unroll
        for (int ssec = 0; ssec < SSPLIT; ssec++) {   // fixed order
            float4 v = ((const float4*)(g_partial + ((size_t)ssec * BB + b) * KD))[k4i];
            acc.x += v.x; acc.y += v.y; acc.z += v.z; acc.w += v.w;
        }
        acc.x *= inv; acc.y *= inv; acc.z *= inv; acc.w *= inv;
        ((float4*)(ctx + (size_t)b * KD))[k4i] = acc;
    }
}

extern "C" void kernel_launch(void* const* d_in, const int* in_sizes, int n_in,
                              void* d_out, int out_size) {
    const int*   mask     = (const int*)d_in[0];
    const float* query    = (const float*)d_in[1];
    const float* proj_key = (const float*)d_in[2];
    const float* value    = (const float*)d_in[3];
    const float* Wq       = (const float*)d_in[4];
    const float* w_energy = (const float*)d_in[5];

    float* out    = (float*)d_out;
    float* ctx    = out;              // (B,1,K) = 32768 floats
    float* alphas = out + BB * KD;    // (B,1,S) = 65536 floats

    k1_proj<<<128, 256>>>(query, Wq);
    k2_scores<<<BB * SS / 8, 256>>>(proj_key, w_energy, mask);
    k4_ctx<<<dim3(KD / 1024, BB, SSPLIT), 256>>>(value);
    k_norm<<<(BB * SS / 4 + BB * KD / 4) / 256, 256>>>(ctx, alphas);
}

// round 11
// speedup vs baseline: 1.6416x; 1.0232x over previous
#include <cuda_runtime.h>

#define BB 16
#define SS 4096
#define HH 1024
#define QD 1024
#define KD 2048
#define SSPLIT 32
#define SCHUNK (SS / SSPLIT)   // 128

// Scratch (no allocation allowed anywhere)
__device__ float g_q[BB * HH];                 // 64 KB
__device__ float g_escore[BB * SS];            // 256 KB unnormalized exp(score)
__device__ float g_partial[SSPLIT * BB * KD];  // 4 MB unnormalized ctx partials
__device__ float g_csum[BB * SSPLIT];          // per-chunk escore sums

__device__ __forceinline__ float tanh_fast(float x) {
    float y;
    asm("tanh.approx.f32 %0, %1;" : "=f"(y) : "f"(x));
    return y;
}

// ---------------------------------------------------------------------------
// K1: q[b,h] = query[b,:]·Wq[h,:].  Warp per h-row, all 16 batches in regs.
// Wq read once (4 MB DRAM); query (64 KB) broadcast from L2. 1024 warps.
// ---------------------------------------------------------------------------
__global__ void __launch_bounds__(256) k1_proj(const float* __restrict__ query,
                                               const float* __restrict__ Wq) {
    int h = (blockIdx.x * blockDim.x + threadIdx.x) >> 5;  // 0..1023
    int lane = threadIdx.x & 31;
    const float4* w4 = (const float4*)(Wq + (size_t)h * QD);
    const float4* q4 = (const float4*)query;

    float acc[BB];
#pragma unroll
    for (int b = 0; b < BB; b++) acc[b] = 0.f;

#pragma unroll
    for (int i = 0; i < QD / 128; i++) {
        float4 w = w4[lane + i * 32];
#pragma unroll
        for (int b = 0; b < BB; b++) {
            float4 q = q4[b * (QD / 4) + lane + i * 32];
            acc[b] += w.x * q.x + w.y * q.y + w.z * q.z + w.w * q.w;
        }
    }
#pragma unroll
    for (int b = 0; b < BB; b++) {
#pragma unroll
        for (int o = 16; o; o >>= 1) acc[b] += __shfl_xor_sync(0xffffffffu, acc[b], o);
    }
    if (lane == 0) {
#pragma unroll
        for (int b = 0; b < BB; b++) g_q[b * HH + h] = acc[b];
    }
}

// ---------------------------------------------------------------------------
// K2: escore[b,s] = mask ? exp(sum_h w[h]*tanh(q[b,h]+pk[b,s,h])) : 0
// Warp per row. MASKED ROWS SKIP THE 4KB proj_key READ (~50% of rows).
// No max-subtraction needed: |score| <= ||w||_1 ~ 16 (clamped at 80).
// ---------------------------------------------------------------------------
__global__ void k2_scores(const float* __restrict__ pk, const float* __restrict__ w_energy,
                          const int* __restrict__ mask) {
    int row = (blockIdx.x * blockDim.x + threadIdx.x) >> 5;  // == b*SS + s
    int lane = threadIdx.x & 31;

    if (mask[row] == 0) {                 // broadcast load, all lanes same addr
        if (lane == 0) g_escore[row] = 0.f;
        return;
    }

    int b = row >> 12;  // / SS
    const float4* p4 = (const float4*)(pk + (size_t)row * HH);
    const float4* q4 = (const float4*)(g_q + (size_t)b * HH);
    const float4* w4 = (const float4*)w_energy;
    float acc = 0.f;
#pragma unroll
    for (int i = 0; i < HH / 128; i++) {
        float4 p = __ldcs(&p4[lane + i * 32]);
        float4 q = q4[lane + i * 32];
        float4 w = w4[lane + i * 32];
        acc += w.x * tanh_fast(q.x + p.x);
        acc += w.y * tanh_fast(q.y + p.y);
        acc += w.z * tanh_fast(q.z + p.z);
        acc += w.w * tanh_fast(q.w + p.w);
    }
#pragma unroll
    for (int o = 16; o; o >>= 1) acc += __shfl_xor_sync(0xffffffffu, acc, o);
    if (lane == 0)
        g_escore[row] = __expf(fminf(acc, 80.f));
}

// ---------------------------------------------------------------------------
// K4: unnormalized partial context with ZERO-ROW SKIP.
// Deterministic in-order compaction of active rows, then MLP-8 loop over the
// compacted list. blockIdx.x==0 block also emits the chunk's escore sum.
// grid = (KD/1024, BB, SSPLIT) = 1024 blocks.
// ---------------------------------------------------------------------------
__global__ void __launch_bounds__(256) k4_ctx(const float* __restrict__ value) {
    __shared__ float a[SCHUNK];
    __shared__ float sa[SCHUNK + 8];
    __shared__ short sidx[SCHUNK + 8];
    __shared__ int warpcnt[4];
    __shared__ int s_nact;
    int b = blockIdx.y;
    int ssec = blockIdx.z;
    int tid = threadIdx.x;
    int s0 = ssec * SCHUNK;

    if (tid < SCHUNK)
        a[tid] = g_escore[b * SS + s0 + tid];
    __syncthreads();

    // in-order compaction (tid order => deterministic)
    if (tid < SCHUNK) {
        bool act = (a[tid] != 0.f);
        unsigned m = __ballot_sync(0xffffffffu, act);
        int lane = tid & 31, w = tid >> 5;
        if (lane == 0) warpcnt[w] = __popc(m);
    }
    __syncthreads();
    if (tid < SCHUNK) {
        bool act = (a[tid] != 0.f);
        unsigned m = __ballot_sync(0xffffffffu, act);
        int lane = tid & 31, w = tid >> 5;
        int base = 0;
#pragma unroll
        for (int i = 0; i < 4; i++) if (i < w) base += warpcnt[i];
        int pos = base + __popc(m & ((1u << lane) - 1u));
        if (act) { sa[pos] = a[tid]; sidx[pos] = (short)tid; }
        if (tid == 0) {
            int n = warpcnt[0] + warpcnt[1] + warpcnt[2] + warpcnt[3];
            int npad = (n + 7) & ~7;
            for (int j = n; j < npad; j++) { sa[j] = 0.f; sidx[j] = 0; }
            s_nact = npad;
            if (blockIdx.x == 0) {                 // chunk sum, fixed order
                float t = 0.f;
                for (int s = 0; s < SCHUNK; s++) t += a[s];
                g_csum[b * SSPLIT + ssec] = t;
            }
        }
    }
    __syncthreads();
    int nact = s_nact;

    int k4i = blockIdx.x * blockDim.x + tid;
    const float4* vp = (const float4*)(value + ((size_t)b * SS + s0) * KD) + k4i;
    float4 acc = make_float4(0.f, 0.f, 0.f, 0.f);
    for (int j = 0; j < nact; j += 8) {
#pragma unroll
        for (int u = 0; u < 8; u++) {
            float al = sa[j + u];
            int s = sidx[j + u];
            float4 v = __ldcs(&vp[(size_t)s * (KD / 4)]);
            acc.x += al * v.x;
            acc.y += al * v.y;
            acc.z += al * v.z;
            acc.w += al * v.w;
        }
    }
    ((float4*)(g_partial + ((size_t)ssec * BB + b) * KD))[k4i] = acc;
}

// ---------------------------------------------------------------------------
// K_norm v2: 192 blocks.
//  blocks [0,64):   alphas = escore * inv   (1 float4/thread)
//  blocks [64,192): ctx — 64 items/block, 4 threads/item (8 partials each,
//                   fixed j-order), smem combine in fixed part-order.
// ---------------------------------------------------------------------------
__global__ void __launch_bounds__(256) k_norm(float* __restrict__ ctx,
                                              float* __restrict__ alphas) {
    int tid = threadIdx.x;
    if (blockIdx.x < 64) {
        int item = blockIdx.x * 256 + tid;      // 0 .. 16383 (float4 over escore)
        int b = item >> 10;                     // / (SS/4)
        float t = 0.f;
#pragma unroll
        for (int i = 0; i < SSPLIT; i++) t += g_csum[b * SSPLIT + i];  // fixed order
        float inv = 1.0f / t;
        float4 e = ((const float4*)g_escore)[item];
        e.x *= inv; e.y *= inv; e.z *= inv; e.w *= inv;
        ((float4*)alphas)[item] = e;
    } else {
        __shared__ float4 red[256];
        int cb = blockIdx.x - 64;               // 0..127
        int local = tid & 63;                   // item within block
        int part = tid >> 6;                    // 0..3
        int ci = cb * 64 + local;               // 0 .. 8191 global ctx float4 item
        int b = ci >> 9;                        // / (KD/4)
        int k4i = ci & (KD / 4 - 1);

        float4 acc = make_float4(0.f, 0.f, 0.f, 0.f);
#pragma unroll
        for (int j = 0; j < 8; j++) {           // fixed order within part
            int ssec = part * 8 + j;
            float4 v = ((const float4*)(g_partial + ((size_t)ssec * BB + b) * KD))[k4i];
            acc.x += v.x; acc.y += v.y; acc.z += v.z; acc.w += v.w;
        }
        red[tid] = acc;
        __syncthreads();
        if (part == 0) {
            float4 s = red[local];              // part 0
#pragma unroll
            for (int p = 1; p < 4; p++) {       // fixed part order
                float4 v = red[p * 64 + local];
                s.x += v.x; s.y += v.y; s.z += v.z; s.w += v.w;
            }
            float t = 0.f;
#pragma unroll
            for (int i = 0; i < SSPLIT; i++) t += g_csum[b * SSPLIT + i];  // fixed order
            float inv = 1.0f / t;
            s.x *= inv; s.y *= inv; s.z *= inv; s.w *= inv;
            ((float4*)(ctx + (size_t)b * KD))[k4i] = s;
        }
    }
}

extern "C" void kernel_launch(void* const* d_in, const int* in_sizes, int n_in,
                              void* d_out, int out_size) {
    const int*   mask     = (const int*)d_in[0];
    const float* query    = (const float*)d_in[1];
    const float* proj_key = (const float*)d_in[2];
    const float* value    = (const float*)d_in[3];
    const float* Wq       = (const float*)d_in[4];
    const float* w_energy = (const float*)d_in[5];

    float* out    = (float*)d_out;
    float* ctx    = out;              // (B,1,K) = 32768 floats
    float* alphas = out + BB * KD;    // (B,1,S) = 65536 floats

    k1_proj<<<128, 256>>>(query, Wq);
    k2_scores<<<BB * SS / 8, 256>>>(proj_key, w_energy, mask);
    k4_ctx<<<dim3(KD / 1024, BB, SSPLIT), 256>>>(value);
    k_norm<<<192, 256>>>(ctx, alphas);
}